// round 6
// baseline (speedup 1.0000x reference)
#include <cuda_runtime.h>
#include <cuda_bf16.h>
#include <cstdint>

#define NN    50000
#define OBS   15
#define H     64
#define TILE  64          // neighbors per block
#define NTHR  256
#define KT    5           // k-tiles of 16 (K = 80: 64 h + x0,x1,1,0 + pad)
#define HAS   44          // hA row stride in u32 (conflict-free)

__device__ float g_social[16 * H];

// ---- bf16 helpers -----------------------------------------------------------
__device__ __forceinline__ uint32_t pack_bf(__nv_bfloat16 lo, __nv_bfloat16 hi) {
    return (uint32_t)__bfloat16_as_ushort(lo) | ((uint32_t)__bfloat16_as_ushort(hi) << 16);
}
__device__ __forceinline__ void bsplit(float v, __nv_bfloat16& h, __nv_bfloat16& l) {
    h = __float2bfloat16_rn(v);
    l = __float2bfloat16_rn(v - __bfloat162float(h));
}
__device__ __forceinline__ float bf_lo(uint32_t w) {
    return __bfloat162float(__ushort_as_bfloat16((unsigned short)(w & 0xffff)));
}
__device__ __forceinline__ float bf_hi(uint32_t w) {
    return __bfloat162float(__ushort_as_bfloat16((unsigned short)(w >> 16)));
}
// ---- activations ------------------------------------------------------------
__device__ __forceinline__ float tanh_ap(float x) {
    float y; asm("tanh.approx.f32 %0, %1;" : "=f"(y) : "f"(x)); return y;
}
__device__ __forceinline__ float sig_ap(float x) { return fmaf(0.5f, tanh_ap(0.5f * x), 0.5f); }
__device__ __forceinline__ float sigf(float x)   { return __fdividef(1.0f, 1.0f + __expf(-x)); }
__device__ __forceinline__ float tanhf_(float x) { return 2.0f * sigf(2.0f * x) - 1.0f; }
// ---- mma.sync m16n8k16 bf16 (sm_80 ISA, valid on sm_100 base) --------------
__device__ __forceinline__ void mma_bf16(float* d, const uint32_t* a, uint32_t b0, uint32_t b1) {
    asm volatile(
        "mma.sync.aligned.m16n8k16.row.col.f32.bf16.bf16.f32 "
        "{%0,%1,%2,%3}, {%4,%5,%6,%7}, {%8,%9}, {%0,%1,%2,%3};"
        : "+f"(d[0]), "+f"(d[1]), "+f"(d[2]), "+f"(d[3])
        : "r"(a[0]), "r"(a[1]), "r"(a[2]), "r"(a[3]), "r"(b0), "r"(b1));
}

// Augmented weight element: Wfull[grow][k], k<64: W_hh; 64,65: W_ih; 66: bias; else 0
__device__ __forceinline__ float wfull(int grow, int k,
                                       const float* Whh, const float* Wih,
                                       const float* bih, const float* bhh) {
    if (k < 64) return Whh[grow * 64 + k];
    if (k == 64) return Wih[2 * grow];
    if (k == 65) return Wih[2 * grow + 1];
    if (k == 66) return bih[grow] + bhh[grow];
    return 0.0f;
}

// ---------------------------------------------------------------------------
// Neighbor LSTM: gates = [h, x, 1] @ Waug^T via compensated bf16 mma.sync.
// Block: 64 neighbors, 8 warps = 4 M-tiles x 2 hidden halves. Gate columns
// permuted so each thread owns i,f,g,o of the same (neighbor, j) cells.
// ---------------------------------------------------------------------------
__global__ void __launch_bounds__(NTHR)
neighbor_kernel(const float* __restrict__ oth,   // (OBS, NN, 2)
                const int*   __restrict__ mask,  // (OBS, NN)
                const float* __restrict__ tgt,   // (OBS, 1, 2)
                const float* __restrict__ W_ih,  // (256, 2)
                const float* __restrict__ b_ih,  // (256)
                const float* __restrict__ W_hh,  // (256, 64)
                const float* __restrict__ b_hh)  // (256)
{
    extern __shared__ uint32_t smu[];
    uint32_t* Wfhi = smu;                        // [2][KT][16][64]  B-frag lanes
    uint32_t* Wflo = Wfhi + 2 * KT * 16 * 64;    // same
    uint32_t* hAhi = Wflo + 2 * KT * 16 * 64;    // [64][HAS] bf16x2 pairs of [h|x|1]
    uint32_t* hAlo = hAhi + 64 * HAS;
    float*    bins = (float*)(hAlo + 64 * HAS);  // [16*64]

    const int tid  = threadIdx.x;
    const int lane = tid & 31;
    const int wid  = tid >> 5;
    const int wm   = wid & 3;          // M-tile (16 neighbors)
    const int wn   = wid >> 2;         // hidden half
    const int g    = lane >> 2;        // groupID (row within tile / col within n-tile)
    const int l4   = lane & 3;
    const int n0   = blockIdx.x * TILE;

    // ---- W fragments (hi/lo), lane-linear for LDS.64 ----
    for (int cb = wid; cb < 2 * KT * 16; cb += 8) {
        int cwn = cb / (KT * 16);
        int ckt = (cb % (KT * 16)) >> 4;
        int cnt = cb & 15;
        int q = cnt >> 2, b = cnt & 3;
        int grow = 64 * q + 32 * cwn + 8 * b + g;
        int k0 = 16 * ckt + 2 * l4;
        float e0 = wfull(grow, k0,     W_hh, W_ih, b_ih, b_hh);
        float e1 = wfull(grow, k0 + 1, W_hh, W_ih, b_ih, b_hh);
        float e2 = wfull(grow, k0 + 8, W_hh, W_ih, b_ih, b_hh);
        float e3 = wfull(grow, k0 + 9, W_hh, W_ih, b_ih, b_hh);
        __nv_bfloat16 h0, l0, h1, l1, h2, l2, h3, l3;
        bsplit(e0, h0, l0); bsplit(e1, h1, l1);
        bsplit(e2, h2, l2); bsplit(e3, h3, l3);
        int base = cb * 64 + 2 * lane;
        Wfhi[base]     = pack_bf(h0, h1);
        Wfhi[base + 1] = pack_bf(h2, h3);
        Wflo[base]     = pack_bf(l0, l1);
        Wflo[base + 1] = pack_bf(l2, l3);
    }
    // ---- hA init: zeros, constant-1 column, x(0) ----
    for (int i = tid; i < 64 * HAS; i += NTHR) { hAhi[i] = 0u; hAlo[i] = 0u; }
    for (int i = tid; i < 16 * H; i += NTHR) bins[i] = 0.0f;
    __syncthreads();
    if (tid < 64) {
        hAhi[tid * HAS + 33] = pack_bf(__float2bfloat16_rn(1.0f), __float2bfloat16_rn(0.0f));
        int gn = n0 + tid;
        float2 xv = make_float2(0.0f, 0.0f);
        if (gn < NN) xv = ((const float2*)oth)[gn];
        __nv_bfloat16 xh0, xl0, xh1, xl1;
        bsplit(xv.x, xh0, xl0); bsplit(xv.y, xh1, xl1);
        hAhi[tid * HAS + 32] = pack_bf(xh0, xh1);
        hAlo[tid * HAS + 32] = pack_bf(xl0, xl1);
    }

    float creg[16];
    #pragma unroll
    for (int i = 0; i < 16; i++) creg[i] = 0.0f;

    const uint2* Wfhi2 = (const uint2*)Wfhi;
    const uint2* Wflo2 = (const uint2*)Wflo;

    #pragma unroll 1
    for (int t = 0; t < OBS; t++) {
        __syncthreads();   // hA (h(t-1), x(t)) ready

        // prefetch x(t+1) (stored in epilogue)
        float2 xn = make_float2(0.0f, 0.0f);
        if (tid < 64 && t + 1 < OBS) {
            int gn = n0 + tid;
            if (gn < NN) xn = ((const float2*)oth)[(size_t)(t + 1) * NN + gn];
        }

        float acc[16][4];
        #pragma unroll
        for (int nt = 0; nt < 16; nt++)
            #pragma unroll
            for (int r = 0; r < 4; r++) acc[nt][r] = 0.0f;

        #pragma unroll 1
        for (int kt = 0; kt < KT; kt++) {
            const int ab = (16 * wm + g) * HAS + 8 * kt + l4;
            uint32_t Ahi[4] = { hAhi[ab], hAhi[ab + 8 * HAS],
                                hAhi[ab + 4], hAhi[ab + 8 * HAS + 4] };
            uint32_t Alo[4] = { hAlo[ab], hAlo[ab + 8 * HAS],
                                hAlo[ab + 4], hAlo[ab + 8 * HAS + 4] };
            const int wb = ((wn * KT + kt) * 16) * 32 + lane;
            #pragma unroll 4
            for (int nt = 0; nt < 16; nt++) {
                uint2 bh = Wfhi2[wb + nt * 32];
                uint2 bl = Wflo2[wb + nt * 32];
                mma_bf16(acc[nt], Ahi, bh.x, bh.y);
                mma_bf16(acc[nt], Ahi, bl.x, bl.y);
                mma_bf16(acc[nt], Alo, bh.x, bh.y);
            }
        }
        __syncthreads();   // all hA reads done; safe to overwrite

        // epilogue: activations (thread-local), write h(t) and x(t+1)
        #pragma unroll
        for (int b = 0; b < 4; b++) {
            #pragma unroll
            for (int r = 0; r < 2; r++) {
                const int row = 16 * wm + g + 8 * r;
                float hc[2];
                #pragma unroll
                for (int c = 0; c < 2; c++) {
                    const int dr = 2 * r + c;
                    float pi = acc[b][dr];
                    float pf = acc[4 + b][dr];
                    float pg = acc[8 + b][dr];
                    float po = acc[12 + b][dr];
                    const int ci = (b * 2 + r) * 2 + c;
                    float cn = fmaf(sig_ap(pf), creg[ci], sig_ap(pi) * tanh_ap(pg));
                    creg[ci] = cn;
                    hc[c] = sig_ap(po) * tanh_ap(cn);
                }
                __nv_bfloat16 hh0, hl0, hh1, hl1;
                bsplit(hc[0], hh0, hl0);
                bsplit(hc[1], hh1, hl1);
                const int jp = 16 * wn + 4 * b + l4;
                hAhi[row * HAS + jp] = pack_bf(hh0, hh1);
                hAlo[row * HAS + jp] = pack_bf(hl0, hl1);
            }
        }
        if (tid < 64 && t + 1 < OBS) {
            __nv_bfloat16 xh0, xl0, xh1, xl1;
            bsplit(xn.x, xh0, xl0); bsplit(xn.y, xh1, xl1);
            hAhi[tid * HAS + 32] = pack_bf(xh0, xh1);
            hAlo[tid * HAS + 32] = pack_bf(xl0, xl1);
        }
    }
    __syncthreads();

    // ---- social pooling at t=14: 4 threads per neighbor, 16 j each ----
    {
        const int nl = tid >> 2;
        const int part = tid & 3;
        const int gn = n0 + nl;
        bool valid = false;
        int bin = 0;
        if (gn < NN) {
            float2 xv = ((const float2*)oth)[(size_t)(OBS - 1) * NN + gn];
            float rx = xv.x - tgt[(OBS - 1) * 2];
            float ry = xv.y - tgt[(OBS - 1) * 2 + 1];
            int m = mask[(size_t)(OBS - 1) * NN + gn];
            bool within = (fabsf(rx) <= 2.0f) && (fabsf(ry) <= 2.0f);
            int cx = (int)truncf(rx) + 2;
            int cy = (int)truncf(ry) + 2;
            valid = within && cx >= 0 && cx < 4 && cy >= 0 && cy < 4 && (m != 0);
            bin = cy * 4 + cx;
        }
        if (valid) {
            #pragma unroll
            for (int p = 0; p < 8; p++) {
                int jp = 8 * part + p;
                uint32_t whi = hAhi[nl * HAS + jp];
                uint32_t wlo = hAlo[nl * HAS + jp];
                float h0 = bf_lo(whi) + bf_lo(wlo);
                float h1 = bf_hi(whi) + bf_hi(wlo);
                atomicAdd(&bins[bin * H + 2 * jp],     h0);
                atomicAdd(&bins[bin * H + 2 * jp + 1], h1);
            }
        }
    }
    __syncthreads();
    for (int i = tid; i < 16 * H; i += NTHR)
        atomicAdd(&g_social[i], bins[i]);
}

// ---------------------------------------------------------------------------
// Head: target LSTM + social MLP + classifier (LDS-resident W_hh).
// ---------------------------------------------------------------------------
__global__ void __launch_bounds__(256)
head_kernel(const float* __restrict__ tgt,
            const float* __restrict__ W_ih, const float* __restrict__ b_ih,
            const float* __restrict__ W_hh, const float* __restrict__ b_hh,
            const float* __restrict__ W1,  const float* __restrict__ b1,
            const float* __restrict__ W2,  const float* __restrict__ b2,
            const float* __restrict__ Wc,  const float* __restrict__ bc,
            float* __restrict__ out)
{
    extern __shared__ float Wr[];                  // [256][65] padded W_hh
    __shared__ float h_s[H], c_s[H], gates[4 * H];
    __shared__ float s1[16 * H], hid[H], comb[H];
    const int tid  = threadIdx.x;
    const int lane = tid & 31;
    const int wid  = tid >> 5;

    for (int idx = tid; idx < 256 * 64; idx += 256)
        Wr[(idx >> 6) * 65 + (idx & 63)] = W_hh[idx];
    if (tid < H) { h_s[tid] = 0.0f; c_s[tid] = 0.0f; }
    const float bb  = b_ih[tid] + b_hh[tid];
    const float wx0 = W_ih[2 * tid];
    const float wx1 = W_ih[2 * tid + 1];
    __syncthreads();

    for (int t = 0; t < OBS; t++) {
        float x0 = tgt[2 * t], x1 = tgt[2 * t + 1];
        float a0 = 0.f, a1 = 0.f, a2 = 0.f, a3 = 0.f;
        const float* wr = Wr + tid * 65;
        #pragma unroll
        for (int k = 0; k < 64; k += 4) {
            a0 = fmaf(wr[k],     h_s[k],     a0);
            a1 = fmaf(wr[k + 1], h_s[k + 1], a1);
            a2 = fmaf(wr[k + 2], h_s[k + 2], a2);
            a3 = fmaf(wr[k + 3], h_s[k + 3], a3);
        }
        gates[tid] = bb + wx0 * x0 + wx1 * x1 + (a0 + a1) + (a2 + a3);
        __syncthreads();
        if (tid < H) {
            float ig = sigf (gates[tid]);
            float fg = sigf (gates[H     + tid]);
            float gg = tanhf_(gates[2*H  + tid]);
            float og = sigf (gates[3*H   + tid]);
            float cn = fg * c_s[tid] + ig * gg;
            c_s[tid] = cn;
            h_s[tid] = og * tanhf_(cn);
        }
        __syncthreads();
    }

    for (int i = tid; i < 16 * H; i += 256) s1[i] = g_social[i];
    __syncthreads();

    for (int r = wid * 8; r < wid * 8 + 8; r++) {
        float p = 0.f;
        #pragma unroll 8
        for (int i = 0; i < 32; i++)
            p = fmaf(W1[r * 1024 + i * 32 + lane], s1[i * 32 + lane], p);
        #pragma unroll
        for (int off = 16; off; off >>= 1) p += __shfl_xor_sync(0xffffffffu, p, off);
        if (lane == 0) hid[r] = fmaxf(p + b1[r], 0.0f);
    }
    __syncthreads();

    for (int r = wid * 8; r < wid * 8 + 8; r++) {
        float p = 0.f;
        #pragma unroll
        for (int i = 0; i < 2; i++)
            p = fmaf(W2[r * 64 + i * 32 + lane], hid[i * 32 + lane], p);
        #pragma unroll
        for (int off = 16; off; off >>= 1) p += __shfl_xor_sync(0xffffffffu, p, off);
        if (lane == 0) comb[r] = h_s[r] + p + b2[r];
    }
    __syncthreads();

    if (wid < 2) {
        float p = 0.f;
        #pragma unroll
        for (int i = 0; i < 2; i++)
            p = fmaf(Wc[wid * 64 + i * 32 + lane], comb[i * 32 + lane], p);
        #pragma unroll
        for (int off = 16; off; off >>= 1) p += __shfl_xor_sync(0xffffffffu, p, off);
        if (lane == 0) out[wid] = p + bc[wid];
    }
}

// ---------------------------------------------------------------------------
extern "C" void kernel_launch(void* const* d_in, const int* in_sizes, int n_in,
                              void* d_out, int out_size)
{
    const float* tgt  = (const float*)d_in[0];
    const float* oth  = (const float*)d_in[1];
    const int*   mask = (const int*)  d_in[2];
    const float* W_ih = (const float*)d_in[3];
    const float* b_ih = (const float*)d_in[4];
    const float* W_hh = (const float*)d_in[5];
    const float* b_hh = (const float*)d_in[6];
    const float* W1   = (const float*)d_in[7];
    const float* b1   = (const float*)d_in[8];
    const float* W2   = (const float*)d_in[9];
    const float* b2   = (const float*)d_in[10];
    const float* Wc   = (const float*)d_in[11];
    const float* bc   = (const float*)d_in[12];

    void* sp = nullptr;
    cudaGetSymbolAddress(&sp, g_social);
    cudaMemsetAsync(sp, 0, 16 * H * sizeof(float));

    // smem: Wf hi+lo 2*(2*5*16*64) u32 + hA hi+lo 2*(64*44) u32 + bins 1024 f
    const int smemN = (2 * (2 * KT * 16 * 64) + 2 * (64 * HAS) + 16 * H) * 4;  // 108544
    cudaFuncSetAttribute((const void*)neighbor_kernel,
                         cudaFuncAttributeMaxDynamicSharedMemorySize, smemN);
    const int smemH = 256 * 65 * 4;
    cudaFuncSetAttribute((const void*)head_kernel,
                         cudaFuncAttributeMaxDynamicSharedMemorySize, smemH);

    int grid = (NN + TILE - 1) / TILE;   // 782 blocks
    neighbor_kernel<<<grid, NTHR, smemN>>>(oth, mask, tgt, W_ih, b_ih, W_hh, b_hh);
    head_kernel<<<1, 256, smemH>>>(tgt, W_ih, b_ih, W_hh, b_hh,
                                   W1, b1, W2, b2, Wc, bc, (float*)d_out);
}

// round 7
// speedup vs baseline: 6.4332x; 6.4332x over previous
#include <cuda_runtime.h>
#include <cstdint>

#define NN    50000
#define OBS   15
#define H     64
#define CH    32           // neighbors per chunk (one ticket)
#define NTHR  256
#define NCTA  296          // persistent CTAs (2 per SM)
#define WP    260          // transposed W_hh row stride (floats)
#define HP    36           // h-state row stride (floats, 16B-aligned rows)

__device__ float    g_social[16 * H];
__device__ unsigned g_cnt;
__device__ unsigned g_tick;
__device__ unsigned g_list[NN];     // packed: idx | (bin << 16)

// ---- activations ------------------------------------------------------------
__device__ __forceinline__ float tanh_ap(float x) {
    float y; asm("tanh.approx.f32 %0, %1;" : "=f"(y) : "f"(x)); return y;
}
__device__ __forceinline__ float sig_ap(float x) { return fmaf(0.5f, tanh_ap(0.5f * x), 0.5f); }
__device__ __forceinline__ float sigf(float x)   { return __fdividef(1.0f, 1.0f + __expf(-x)); }
__device__ __forceinline__ float tanhf_(float x) { return 2.0f * sigf(2.0f * x) - 1.0f; }

// ---------------------------------------------------------------------------
// Filter: keep only neighbors that contribute to the (only live) final-step
// social pooling: mask[14]!=0 and inside the 4x4 window around tgt[14].
// ---------------------------------------------------------------------------
__global__ void __launch_bounds__(256)
filter_kernel(const float* __restrict__ oth, const int* __restrict__ mask,
              const float* __restrict__ tgt)
{
    int n = blockIdx.x * blockDim.x + threadIdx.x;
    bool valid = false; int bin = 0;
    if (n < NN) {
        float2 xv = ((const float2*)oth)[(size_t)(OBS - 1) * NN + n];
        float rx = xv.x - tgt[(OBS - 1) * 2];
        float ry = xv.y - tgt[(OBS - 1) * 2 + 1];
        int m = mask[(size_t)(OBS - 1) * NN + n];
        bool within = (fabsf(rx) <= 2.0f) && (fabsf(ry) <= 2.0f);
        int cx = (int)truncf(rx) + 2;
        int cy = (int)truncf(ry) + 2;
        valid = within && cx >= 0 && cx < 4 && cy >= 0 && cy < 4 && (m != 0);
        bin = cy * 4 + cx;
    }
    unsigned ball = __ballot_sync(0xffffffffu, valid);
    int lane = threadIdx.x & 31;
    unsigned base = 0;
    if (lane == 0 && ball) base = atomicAdd(&g_cnt, (unsigned)__popc(ball));
    base = __shfl_sync(0xffffffffu, base, 0);
    if (valid) {
        int rank = __popc(ball & ((1u << lane) - 1u));
        g_list[base + rank] = (unsigned)n | ((unsigned)bin << 16);
    }
}

// ---------------------------------------------------------------------------
// Persistent neighbor LSTM over the compacted list. Weights staged once per
// CTA; atomic tickets hand out 32-neighbor chunks. Thread (tx,ty) owns
// neighbors 4ty..4ty+3 and hidden units 2tx,2tx+1 (all 4 gates) -> c-state
// and activations thread-local. Pure fp32 FFMA (proven roofline path).
// ---------------------------------------------------------------------------
__global__ void __launch_bounds__(NTHR)
neighbor_kernel(const float* __restrict__ oth,   // (OBS, NN, 2)
                const float* __restrict__ W_ih,  // (256, 2)
                const float* __restrict__ b_ih,  // (256)
                const float* __restrict__ W_hh,  // (256, 64)
                const float* __restrict__ b_hh)  // (256)
{
    extern __shared__ float sm[];
    float* Ws   = sm;                 // [64][WP]  Ws[k][j] = W_hh[j][k]
    float* hs   = Ws + H * WP;        // [64][HP]  h state (hidden-major)
    float* bins = hs + H * HP;        // [16*64]   per-CTA social partials

    __shared__ unsigned slots[CH];
    __shared__ float    xs[2 * CH];
    __shared__ unsigned s_tick;

    const int tid = threadIdx.x;
    const int tx  = tid & 31;
    const int ty  = tid >> 5;

    // stage W_hh transposed (once per CTA)
    for (int idx = tid; idx < 4 * H * H; idx += NTHR) {
        int j = idx >> 6, k = idx & 63;
        Ws[k * WP + j] = W_hh[idx];
    }
    for (int i = tid; i < 16 * H; i += NTHR) bins[i] = 0.0f;

    // per-thread gate-row constants: slot g=2q+u -> row j = 64q + 2tx + u
    float wx0[8], wx1[8], bb[8];
    #pragma unroll
    for (int q = 0; q < 4; q++)
        #pragma unroll
        for (int u = 0; u < 2; u++) {
            int j = 64 * q + 2 * tx + u;
            wx0[q * 2 + u] = W_ih[2 * j];
            wx1[q * 2 + u] = W_ih[2 * j + 1];
            bb [q * 2 + u] = b_ih[j] + b_hh[j];
        }

    const unsigned cnt = g_cnt;

    while (true) {
        if (tid == 0) s_tick = atomicAdd(&g_tick, 1u);
        __syncthreads();                 // s_tick ready; prev chunk's hs reads done
        const unsigned base = s_tick * CH;
        if (base >= cnt) break;          // block-uniform

        // zero h state, load chunk slots
        for (int i = tid; i < H * HP; i += NTHR) hs[i] = 0.0f;
        if (tid < CH)
            slots[tid] = (base + tid < cnt) ? g_list[base + tid] : 0xffffffffu;
        __syncthreads();

        if (tid < CH) {
            unsigned pk = slots[tid];
            float2 xv = make_float2(0.0f, 0.0f);
            if (pk != 0xffffffffu)
                xv = ((const float2*)oth)[pk & 0xffffu];   // x(0)
            xs[2 * tid] = xv.x; xs[2 * tid + 1] = xv.y;
        }

        float creg[4][2];
        #pragma unroll
        for (int i = 0; i < 4; i++) { creg[i][0] = 0.0f; creg[i][1] = 0.0f; }

        #pragma unroll 1
        for (int t = 0; t < OBS; t++) {
            __syncthreads();             // xs(t) and hs(t-1) ready

            // prefetch x(t+1)
            float2 xn = make_float2(0.0f, 0.0f);
            if (tid < CH && t + 1 < OBS) {
                unsigned pk = slots[tid];
                if (pk != 0xffffffffu)
                    xn = ((const float2*)oth)[(size_t)(t + 1) * NN + (pk & 0xffffu)];
            }

            // acc[i][2q+u] = bias + W_ih * x
            float acc[4][8];
            #pragma unroll
            for (int i = 0; i < 4; i++) {
                float x0 = xs[2 * (4 * ty + i)];
                float x1 = xs[2 * (4 * ty + i) + 1];
                #pragma unroll
                for (int g = 0; g < 8; g++)
                    acc[i][g] = fmaf(wx1[g], x1, fmaf(wx0[g], x0, bb[g]));
            }

            // GEMM: acc += h @ W_hh^T (h broadcast per warp)
            const float* hrow = hs + 4 * ty;
            const float* wcol = Ws + 2 * tx;
            #pragma unroll 8
            for (int k = 0; k < H; k++) {
                float4 h4 = *(const float4*)(hrow + k * HP);
                float2 w0 = *(const float2*)(wcol + k * WP);
                float2 w1 = *(const float2*)(wcol + k * WP + 64);
                float2 w2 = *(const float2*)(wcol + k * WP + 128);
                float2 w3 = *(const float2*)(wcol + k * WP + 192);
                float hh[4] = {h4.x, h4.y, h4.z, h4.w};
                #pragma unroll
                for (int i = 0; i < 4; i++) {
                    acc[i][0] = fmaf(w0.x, hh[i], acc[i][0]);
                    acc[i][1] = fmaf(w0.y, hh[i], acc[i][1]);
                    acc[i][2] = fmaf(w1.x, hh[i], acc[i][2]);
                    acc[i][3] = fmaf(w1.y, hh[i], acc[i][3]);
                    acc[i][4] = fmaf(w2.x, hh[i], acc[i][4]);
                    acc[i][5] = fmaf(w2.y, hh[i], acc[i][5]);
                    acc[i][6] = fmaf(w3.x, hh[i], acc[i][6]);
                    acc[i][7] = fmaf(w3.y, hh[i], acc[i][7]);
                }
            }
            __syncthreads();             // all hs/xs reads done

            // LSTM nonlinearity (thread-local), write h(t)
            float hnew[4][2];
            #pragma unroll
            for (int i = 0; i < 4; i++)
                #pragma unroll
                for (int u = 0; u < 2; u++) {
                    float ig = sig_ap (acc[i][0 + u]);
                    float fg = sig_ap (acc[i][2 + u]);
                    float gg = tanh_ap(acc[i][4 + u]);
                    float og = sig_ap (acc[i][6 + u]);
                    float c  = fmaf(fg, creg[i][u], ig * gg);
                    creg[i][u] = c;
                    hnew[i][u] = og * tanh_ap(c);
                }
            #pragma unroll
            for (int u = 0; u < 2; u++) {
                float4 v = {hnew[0][u], hnew[1][u], hnew[2][u], hnew[3][u]};
                *(float4*)(hs + (2 * tx + u) * HP + 4 * ty) = v;
            }
            if (tid < CH && t + 1 < OBS) {
                xs[2 * tid] = xn.x; xs[2 * tid + 1] = xn.y;
            }
        }
        __syncthreads();                 // final h visible

        // pooling: 8 threads per slot, 8 hidden units each
        {
            int s = tid >> 3, part = tid & 7;
            unsigned pk = slots[s];
            if (pk != 0xffffffffu) {
                int bin = (int)(pk >> 16);
                #pragma unroll
                for (int p = 0; p < 8; p++) {
                    int j = part * 8 + p;
                    atomicAdd(&bins[bin * H + j], hs[j * HP + s]);
                }
            }
        }
    }
    __syncthreads();
    for (int i = tid; i < 16 * H; i += NTHR)
        atomicAdd(&g_social[i], bins[i]);
}

// ---------------------------------------------------------------------------
// Head: target LSTM + social MLP + classifier.
// ---------------------------------------------------------------------------
__global__ void __launch_bounds__(256)
head_kernel(const float* __restrict__ tgt,
            const float* __restrict__ W_ih, const float* __restrict__ b_ih,
            const float* __restrict__ W_hh, const float* __restrict__ b_hh,
            const float* __restrict__ W1,  const float* __restrict__ b1,
            const float* __restrict__ W2,  const float* __restrict__ b2,
            const float* __restrict__ Wc,  const float* __restrict__ bc,
            float* __restrict__ out)
{
    extern __shared__ float Wr[];                  // [256][65] padded W_hh
    __shared__ float h_s[H], c_s[H], gates[4 * H];
    __shared__ float s1[16 * H], hid[H], comb[H];
    const int tid  = threadIdx.x;
    const int lane = tid & 31;
    const int wid  = tid >> 5;

    for (int idx = tid; idx < 4 * H * H; idx += 256)
        Wr[(idx >> 6) * 65 + (idx & 63)] = W_hh[idx];
    if (tid < H) { h_s[tid] = 0.0f; c_s[tid] = 0.0f; }
    const float bb  = b_ih[tid] + b_hh[tid];
    const float wx0 = W_ih[2 * tid];
    const float wx1 = W_ih[2 * tid + 1];
    __syncthreads();

    for (int t = 0; t < OBS; t++) {
        float x0 = tgt[2 * t], x1 = tgt[2 * t + 1];
        float a0 = 0.f, a1 = 0.f, a2 = 0.f, a3 = 0.f;
        const float* wr = Wr + tid * 65;
        #pragma unroll
        for (int k = 0; k < H; k += 4) {
            a0 = fmaf(wr[k],     h_s[k],     a0);
            a1 = fmaf(wr[k + 1], h_s[k + 1], a1);
            a2 = fmaf(wr[k + 2], h_s[k + 2], a2);
            a3 = fmaf(wr[k + 3], h_s[k + 3], a3);
        }
        gates[tid] = bb + wx0 * x0 + wx1 * x1 + (a0 + a1) + (a2 + a3);
        __syncthreads();
        if (tid < H) {
            float ig = sigf (gates[tid]);
            float fg = sigf (gates[H     + tid]);
            float gg = tanhf_(gates[2*H  + tid]);
            float og = sigf (gates[3*H   + tid]);
            float cn = fg * c_s[tid] + ig * gg;
            c_s[tid] = cn;
            h_s[tid] = og * tanhf_(cn);
        }
        __syncthreads();
    }

    for (int i = tid; i < 16 * H; i += 256) s1[i] = g_social[i];
    __syncthreads();

    // hid = relu(W1 @ s1 + b1): 8 independent row-chains per warp (unrolled)
    #pragma unroll
    for (int rr = 0; rr < 8; rr++) {
        int r = wid * 8 + rr;
        float p = 0.f;
        #pragma unroll 8
        for (int i = 0; i < 32; i++)
            p = fmaf(W1[r * 1024 + i * 32 + lane], s1[i * 32 + lane], p);
        #pragma unroll
        for (int off = 16; off; off >>= 1) p += __shfl_xor_sync(0xffffffffu, p, off);
        if (lane == 0) hid[r] = fmaxf(p + b1[r], 0.0f);
    }
    __syncthreads();

    #pragma unroll
    for (int rr = 0; rr < 8; rr++) {
        int r = wid * 8 + rr;
        float p = 0.f;
        #pragma unroll
        for (int i = 0; i < 2; i++)
            p = fmaf(W2[r * 64 + i * 32 + lane], hid[i * 32 + lane], p);
        #pragma unroll
        for (int off = 16; off; off >>= 1) p += __shfl_xor_sync(0xffffffffu, p, off);
        if (lane == 0) comb[r] = h_s[r] + p + b2[r];
    }
    __syncthreads();

    if (wid < 2) {
        float p = 0.f;
        #pragma unroll
        for (int i = 0; i < 2; i++)
            p = fmaf(Wc[wid * 64 + i * 32 + lane], comb[i * 32 + lane], p);
        #pragma unroll
        for (int off = 16; off; off >>= 1) p += __shfl_xor_sync(0xffffffffu, p, off);
        if (lane == 0) out[wid] = p + bc[wid];
    }
}

// ---------------------------------------------------------------------------
extern "C" void kernel_launch(void* const* d_in, const int* in_sizes, int n_in,
                              void* d_out, int out_size)
{
    const float* tgt  = (const float*)d_in[0];
    const float* oth  = (const float*)d_in[1];
    const int*   mask = (const int*)  d_in[2];
    const float* W_ih = (const float*)d_in[3];
    const float* b_ih = (const float*)d_in[4];
    const float* W_hh = (const float*)d_in[5];
    const float* b_hh = (const float*)d_in[6];
    const float* W1   = (const float*)d_in[7];
    const float* b1   = (const float*)d_in[8];
    const float* W2   = (const float*)d_in[9];
    const float* b2   = (const float*)d_in[10];
    const float* Wc   = (const float*)d_in[11];
    const float* bc   = (const float*)d_in[12];

    void* p;
    cudaGetSymbolAddress(&p, g_social); cudaMemsetAsync(p, 0, 16 * H * sizeof(float));
    cudaGetSymbolAddress(&p, g_cnt);    cudaMemsetAsync(p, 0, sizeof(unsigned));
    cudaGetSymbolAddress(&p, g_tick);   cudaMemsetAsync(p, 0, sizeof(unsigned));

    const int smemN = (H * WP + H * HP + 16 * H) * 4;   // 79872 B
    cudaFuncSetAttribute((const void*)neighbor_kernel,
                         cudaFuncAttributeMaxDynamicSharedMemorySize, smemN);
    const int smemH = 256 * 65 * 4;
    cudaFuncSetAttribute((const void*)head_kernel,
                         cudaFuncAttributeMaxDynamicSharedMemorySize, smemH);

    filter_kernel<<<(NN + 255) / 256, 256>>>(oth, mask, tgt);
    neighbor_kernel<<<NCTA, NTHR, smemN>>>(oth, W_ih, b_ih, W_hh, b_hh);
    head_kernel<<<1, 256, smemH>>>(tgt, W_ih, b_ih, W_hh, b_hh,
                                   W1, b1, W2, b2, Wc, bc, (float*)d_out);
}

// round 10
// speedup vs baseline: 6.9007x; 1.0727x over previous
#include <cuda_runtime.h>
#include <cstdint>

#define NN    50000
#define OBS   15
#define H     64
#define NTHR  256
#define NCTA  296          // persistent CTAs (2 per SM)
#define WP    260          // transposed W_hh row stride (floats)

__device__ float    g_social[16 * H];
__device__ float    g_ht[H];        // final target-LSTM hidden state
__device__ unsigned g_cnt;
__device__ unsigned g_tick;
__device__ unsigned g_list[NN];     // packed: idx | (bin << 16)

// ---- activations ------------------------------------------------------------
__device__ __forceinline__ float tanh_ap(float x) {
    float y; asm("tanh.approx.f32 %0, %1;" : "=f"(y) : "f"(x)); return y;
}
__device__ __forceinline__ float sig_ap(float x) { return fmaf(0.5f, tanh_ap(0.5f * x), 0.5f); }
__device__ __forceinline__ float sigf(float x)   { return __fdividef(1.0f, 1.0f + __expf(-x)); }
__device__ __forceinline__ float tanhf_(float x) { return 2.0f * sigf(2.0f * x) - 1.0f; }

// ---------------------------------------------------------------------------
// Filter: keep neighbors with mask[14]!=0 inside the 4x4 window around
// tgt[14] — the only ones whose LSTM output is ever used.
// ---------------------------------------------------------------------------
__global__ void __launch_bounds__(256)
filter_kernel(const float* __restrict__ oth, const int* __restrict__ mask,
              const float* __restrict__ tgt)
{
    int n = blockIdx.x * blockDim.x + threadIdx.x;
    bool valid = false; int bin = 0;
    if (n < NN) {
        float2 xv = ((const float2*)oth)[(size_t)(OBS - 1) * NN + n];
        float rx = xv.x - tgt[(OBS - 1) * 2];
        float ry = xv.y - tgt[(OBS - 1) * 2 + 1];
        int m = mask[(size_t)(OBS - 1) * NN + n];
        bool within = (fabsf(rx) <= 2.0f) && (fabsf(ry) <= 2.0f);
        int cx = (int)truncf(rx) + 2;
        int cy = (int)truncf(ry) + 2;
        valid = within && cx >= 0 && cx < 4 && cy >= 0 && cy < 4 && (m != 0);
        bin = cy * 4 + cx;
    }
    unsigned ball = __ballot_sync(0xffffffffu, valid);
    int lane = threadIdx.x & 31;
    unsigned base = 0;
    if (lane == 0 && ball) base = atomicAdd(&g_cnt, (unsigned)__popc(ball));
    base = __shfl_sync(0xffffffffu, base, 0);
    if (valid) {
        int rank = __popc(ball & ((1u << lane) - 1u));
        g_list[base + rank] = (unsigned)n | ((unsigned)bin << 16);
    }
}

// ---------------------------------------------------------------------------
// Persistent neighbor LSTM, warp-autonomous: each warp pulls tickets of 4
// neighbors; its h state lives in a private 256-float smem buffer; mainloop
// has no CTA barriers. Thread owns hidden units 2*lane, 2*lane+1 of all 4
// gates for all 4 neighbors -> c-state and activations thread-local.
// Warp 0 of CTA 0 first runs the 15-step target LSTM (exact activations,
// overlapped with other warps' ticket work), then joins the ticket loop.
// ---------------------------------------------------------------------------
__global__ void __launch_bounds__(NTHR)
neighbor_kernel(const float* __restrict__ oth,   // (OBS, NN, 2)
                const float* __restrict__ tgt,   // (OBS, 1, 2)
                const float* __restrict__ W_ih,  // (256, 2)
                const float* __restrict__ b_ih,  // (256)
                const float* __restrict__ W_hh,  // (256, 64)
                const float* __restrict__ b_hh)  // (256)
{
    extern __shared__ float sm[];
    float* Ws   = sm;                 // [64][WP]  Ws[k][j] = W_hh[j][k]
    float* hsA  = Ws + H * WP;        // [8][64][4] per-warp h, layout [j][i]
    float* bins = hsA + 8 * H * 4;    // [16*64]

    const int tid  = threadIdx.x;
    const int lane = tid & 31;
    const int wid  = tid >> 5;
    float* hw = hsA + wid * (H * 4);

    // stage W_hh transposed (once per CTA)
    for (int idx = tid; idx < 4 * H * H; idx += NTHR) {
        int j = idx >> 6, k = idx & 63;
        Ws[k * WP + j] = W_hh[idx];
    }
    for (int i = tid; i < 16 * H; i += NTHR) bins[i] = 0.0f;

    // per-thread gate-row constants: slot g=2q+u -> row j = 64q + 2*lane + u
    float wx0[8], wx1[8], bb[8];
    #pragma unroll
    for (int q = 0; q < 4; q++)
        #pragma unroll
        for (int u = 0; u < 2; u++) {
            int j = 64 * q + 2 * lane + u;
            wx0[q * 2 + u] = W_ih[2 * j];
            wx1[q * 2 + u] = W_ih[2 * j + 1];
            bb [q * 2 + u] = b_ih[j] + b_hh[j];
        }
    __syncthreads();   // Ws ready

    // ---- target LSTM: warp 0 of CTA 0, overlapped with ticket work --------
    if (blockIdx.x == 0 && wid == 0) {
        // lane owns hidden units lane (u=0) and lane+32 (u=1); slot g=2q+u
        float bbT[8], wT0[8], wT1[8];
        #pragma unroll
        for (int q = 0; q < 4; q++)
            #pragma unroll
            for (int u = 0; u < 2; u++) {
                int j = 64 * q + lane + 32 * u;
                bbT[2 * q + u] = b_ih[j] + b_hh[j];
                wT0[2 * q + u] = W_ih[2 * j];
                wT1[2 * q + u] = W_ih[2 * j + 1];
            }
        float h0 = 0.f, h1 = 0.f, c0 = 0.f, c1 = 0.f;
        for (int t = 0; t < OBS; t++) {
            float x0 = tgt[2 * t], x1 = tgt[2 * t + 1];
            float a[8];
            #pragma unroll
            for (int g = 0; g < 8; g++)
                a[g] = fmaf(wT1[g], x1, fmaf(wT0[g], x0, bbT[g]));
            #pragma unroll 4
            for (int k = 0; k < 32; k++) {
                float hk0 = __shfl_sync(0xffffffffu, h0, k);
                float hk1 = __shfl_sync(0xffffffffu, h1, k);
                #pragma unroll
                for (int g = 0; g < 8; g++) {
                    int j = 64 * (g >> 1) + lane + 32 * (g & 1);
                    a[g] = fmaf(Ws[k * WP + j], hk0, a[g]);
                    a[g] = fmaf(Ws[(k + 32) * WP + j], hk1, a[g]);
                }
            }
            // exact activations on the target path
            float i0 = sigf(a[0]), f0 = sigf(a[2]), g0 = tanhf_(a[4]), o0 = sigf(a[6]);
            float i1 = sigf(a[1]), f1 = sigf(a[3]), g1 = tanhf_(a[5]), o1 = sigf(a[7]);
            c0 = fmaf(f0, c0, i0 * g0);  h0 = o0 * tanhf_(c0);
            c1 = fmaf(f1, c1, i1 * g1);  h1 = o1 * tanhf_(c1);
        }
        g_ht[lane]      = h0;
        g_ht[lane + 32] = h1;
    }

    const unsigned cnt = g_cnt;

    while (true) {
        unsigned tk = 0;
        if (lane == 0) tk = atomicAdd(&g_tick, 1u);
        tk = __shfl_sync(0xffffffffu, tk, 0);
        const unsigned base = tk * 4;
        if (base >= cnt) break;          // warp-uniform

        // slots + x(0): lanes 0..3 own one neighbor each
        unsigned pk = 0xffffffffu;
        float2 xv = make_float2(0.0f, 0.0f);
        if (lane < 4 && base + lane < cnt) {
            pk = g_list[base + lane];
            xv = ((const float2*)oth)[pk & 0xffffu];
        }

        // zero this warp's h buffer (rows 2*lane, 2*lane+1)
        *(float4*)(hw + (2 * lane)     * 4) = make_float4(0.f, 0.f, 0.f, 0.f);
        *(float4*)(hw + (2 * lane + 1) * 4) = make_float4(0.f, 0.f, 0.f, 0.f);

        float creg[4][2];
        #pragma unroll
        for (int i = 0; i < 4; i++) { creg[i][0] = 0.0f; creg[i][1] = 0.0f; }

        #pragma unroll 1
        for (int t = 0; t < OBS; t++) {
            __syncwarp();   // h(t-1) writes visible

            float xi0[4], xi1[4];
            #pragma unroll
            for (int i = 0; i < 4; i++) {
                xi0[i] = __shfl_sync(0xffffffffu, xv.x, i);
                xi1[i] = __shfl_sync(0xffffffffu, xv.y, i);
            }
            // prefetch x(t+1)
            float2 xn = make_float2(0.0f, 0.0f);
            if (lane < 4 && t + 1 < OBS && pk != 0xffffffffu)
                xn = ((const float2*)oth)[(size_t)(t + 1) * NN + (pk & 0xffffu)];

            float acc[4][8];
            #pragma unroll
            for (int i = 0; i < 4; i++)
                #pragma unroll
                for (int g = 0; g < 8; g++)
                    acc[i][g] = fmaf(wx1[g], xi1[i], fmaf(wx0[g], xi0[i], bb[g]));

            const float* wcol = Ws + 2 * lane;
            #pragma unroll 8
            for (int k = 0; k < H; k++) {
                float4 h4 = *(const float4*)(hw + k * 4);   // warp-broadcast
                float2 w0 = *(const float2*)(wcol + k * WP);
                float2 w1 = *(const float2*)(wcol + k * WP + 64);
                float2 w2 = *(const float2*)(wcol + k * WP + 128);
                float2 w3 = *(const float2*)(wcol + k * WP + 192);
                float hh[4] = {h4.x, h4.y, h4.z, h4.w};
                #pragma unroll
                for (int i = 0; i < 4; i++) {
                    acc[i][0] = fmaf(w0.x, hh[i], acc[i][0]);
                    acc[i][1] = fmaf(w0.y, hh[i], acc[i][1]);
                    acc[i][2] = fmaf(w1.x, hh[i], acc[i][2]);
                    acc[i][3] = fmaf(w1.y, hh[i], acc[i][3]);
                    acc[i][4] = fmaf(w2.x, hh[i], acc[i][4]);
                    acc[i][5] = fmaf(w2.y, hh[i], acc[i][5]);
                    acc[i][6] = fmaf(w3.x, hh[i], acc[i][6]);
                    acc[i][7] = fmaf(w3.y, hh[i], acc[i][7]);
                }
            }
            __syncwarp();   // all h reads done before overwrite

            float hnew[4][2];
            #pragma unroll
            for (int i = 0; i < 4; i++)
                #pragma unroll
                for (int u = 0; u < 2; u++) {
                    float ig = sig_ap (acc[i][0 + u]);
                    float fg = sig_ap (acc[i][2 + u]);
                    float gg = tanh_ap(acc[i][4 + u]);
                    float og = sig_ap (acc[i][6 + u]);
                    float c  = fmaf(fg, creg[i][u], ig * gg);
                    creg[i][u] = c;
                    hnew[i][u] = og * tanh_ap(c);
                }
            #pragma unroll
            for (int u = 0; u < 2; u++) {
                float4 v = {hnew[0][u], hnew[1][u], hnew[2][u], hnew[3][u]};
                *(float4*)(hw + (2 * lane + u) * 4) = v;
            }
            xv = xn;
        }
        __syncwarp();

        // pooling: lane handles j = lane and j = lane+32 for the 4 neighbors
        #pragma unroll
        for (int i = 0; i < 4; i++) {
            unsigned pki = __shfl_sync(0xffffffffu, pk, i);
            if (pki != 0xffffffffu) {
                int bin = (int)(pki >> 16);
                atomicAdd(&bins[bin * H + lane],      hw[lane * 4 + i]);
                atomicAdd(&bins[bin * H + lane + 32], hw[(lane + 32) * 4 + i]);
            }
        }
    }
    __syncthreads();
    for (int i = tid; i < 16 * H; i += NTHR)
        atomicAdd(&g_social[i], bins[i]);
}

// ---------------------------------------------------------------------------
// MLP epilogue: ctx = relu(s1 @ W1^T + b1) @ W2^T + b2; out = Wc(h_t+ctx)+bc.
// ---------------------------------------------------------------------------
__global__ void __launch_bounds__(256)
mlp_kernel(const float* __restrict__ W1, const float* __restrict__ b1,
           const float* __restrict__ W2, const float* __restrict__ b2,
           const float* __restrict__ Wc, const float* __restrict__ bc,
           float* __restrict__ out)
{
    __shared__ float s1[16 * H], hid[H], comb[H];
    const int tid  = threadIdx.x;
    const int lane = tid & 31;
    const int wid  = tid >> 5;

    for (int i = tid; i < 16 * H; i += 256) s1[i] = g_social[i];
    __syncthreads();

    // hid = relu(W1 @ s1 + b1): 8 independent row-chains per warp
    #pragma unroll
    for (int rr = 0; rr < 8; rr++) {
        int r = wid * 8 + rr;
        float p = 0.f;
        #pragma unroll 8
        for (int i = 0; i < 32; i++)
            p = fmaf(W1[r * 1024 + i * 32 + lane], s1[i * 32 + lane], p);
        #pragma unroll
        for (int off = 16; off; off >>= 1) p += __shfl_xor_sync(0xffffffffu, p, off);
        if (lane == 0) hid[r] = fmaxf(p + b1[r], 0.0f);
    }
    __syncthreads();

    #pragma unroll
    for (int rr = 0; rr < 8; rr++) {
        int r = wid * 8 + rr;
        float p = 0.f;
        #pragma unroll
        for (int i = 0; i < 2; i++)
            p = fmaf(W2[r * 64 + i * 32 + lane], hid[i * 32 + lane], p);
        #pragma unroll
        for (int off = 16; off; off >>= 1) p += __shfl_xor_sync(0xffffffffu, p, off);
        if (lane == 0) comb[r] = g_ht[r] + p + b2[r];
    }
    __syncthreads();

    if (wid < 2) {
        float p = 0.f;
        #pragma unroll
        for (int i = 0; i < 2; i++)
            p = fmaf(Wc[wid * 64 + i * 32 + lane], comb[i * 32 + lane], p);
        #pragma unroll
        for (int off = 16; off; off >>= 1) p += __shfl_xor_sync(0xffffffffu, p, off);
        if (lane == 0) out[wid] = p + bc[wid];
    }
}

// ---------------------------------------------------------------------------
extern "C" void kernel_launch(void* const* d_in, const int* in_sizes, int n_in,
                              void* d_out, int out_size)
{
    const float* tgt  = (const float*)d_in[0];
    const float* oth  = (const float*)d_in[1];
    const int*   mask = (const int*)  d_in[2];
    const float* W_ih = (const float*)d_in[3];
    const float* b_ih = (const float*)d_in[4];
    const float* W_hh = (const float*)d_in[5];
    const float* b_hh = (const float*)d_in[6];
    const float* W1   = (const float*)d_in[7];
    const float* b1   = (const float*)d_in[8];
    const float* W2   = (const float*)d_in[9];
    const float* b2   = (const float*)d_in[10];
    const float* Wc   = (const float*)d_in[11];
    const float* bc   = (const float*)d_in[12];

    void* p;
    cudaGetSymbolAddress(&p, g_social); cudaMemsetAsync(p, 0, 16 * H * sizeof(float));
    cudaGetSymbolAddress(&p, g_cnt);    cudaMemsetAsync(p, 0, sizeof(unsigned));
    cudaGetSymbolAddress(&p, g_tick);   cudaMemsetAsync(p, 0, sizeof(unsigned));

    const int smemN = (H * WP + 8 * H * 4 + 16 * H) * 4;   // 78848 B
    cudaFuncSetAttribute((const void*)neighbor_kernel,
                         cudaFuncAttributeMaxDynamicSharedMemorySize, smemN);

    filter_kernel<<<(NN + 255) / 256, 256>>>(oth, mask, tgt);
    neighbor_kernel<<<NCTA, NTHR, smemN>>>(oth, tgt, W_ih, b_ih, W_hh, b_hh);
    mlp_kernel<<<1, 256>>>(W1, b1, W2, b2, Wc, bc, (float*)d_out);
}